// round 13
// baseline (speedup 1.0000x reference)
#include <cuda_runtime.h>
#include <cstdint>

#define F_DIM 16384
#define N_BINS 128
#define NT 512
#define N_ROWS 4096
#define N_OUT 64
#define GRID_P (152 * 2)      // persistent: 2 CTAs/SM x 152 SMs (GB300)
#define NW 16                 // warps per CTA

// Dynamic smem layout (bytes)
#define SM_HIST 0             // 16 warps * 4096 B = 65536
#define SM_RED  65536         // 32 floats = 128
#define SM_PCNT 65664         // 16 warps * 33 uint4 = 8448
#define SM_CNT  74112         // 128 floats = 512
#define SM_PART 74624         // 512 floats = 2048
#define SM_TOTAL 76672

// Prep outputs (allocation-free static scratch)
__device__ float g_wt[N_BINS * N_OUT];   // W[:, :128] transposed to [bin][out]
__device__ float g_s0[N_OUT];            // sum_j W[o][128+j]
__device__ float g_s1[N_OUT];            // sum_j (j/128) W[o][128+j]

__device__ __forceinline__ float f_inf() { return __int_as_float(0x7f800000); }

// ---------------------------------------------------------------------------
// Prep: one CTA per output o. Transpose counts-half of W to bin-major and
// reduce the 129 boundary weights to S0/S1.
// ---------------------------------------------------------------------------
__global__ __launch_bounds__(128) void prep_kernel(const float* __restrict__ W) {
    __shared__ float sp0[4], sp1[4];
    const int o = blockIdx.x;
    const int tid = threadIdx.x;

    g_wt[tid * N_OUT + o] = W[o * 257 + tid];

    float wv = W[o * 257 + 128 + tid];
    float s0 = wv;
    float s1 = (float)tid * 0.0078125f * wv;     // exact j/128
    if (tid == 0) {
        float w128 = W[o * 257 + 256];
        s0 += w128;
        s1 += w128;                               // t(128) = 1.0
    }
#pragma unroll
    for (int off = 16; off > 0; off >>= 1) {
        s0 += __shfl_xor_sync(0xFFFFFFFFu, s0, off);
        s1 += __shfl_xor_sync(0xFFFFFFFFu, s1, off);
    }
    if ((tid & 31) == 0) { sp0[tid >> 5] = s0; sp1[tid >> 5] = s1; }
    __syncthreads();
    if (tid == 0) {
        g_s0[o] = sp0[0] + sp0[1] + sp0[2] + sp0[3];
        g_s1[o] = sp1[0] + sp1[1] + sp1[2] + sp1[3];
    }
}

// ---------------------------------------------------------------------------
// Persistent fused kernel, NT=512 (16 warps), 2 CTAs/SM -> 32 warps/SM.
// 8 float4/thread fully register-resident; warp-private histograms with the
// bank-invariant layout: counter (w, b, l) at byte
//     w*4096 + (b>>2)*128 + l*4 + (b&3)
//   -> word = w*1024 + (b>>2)*32 + l -> bank = l for ANY bin (CF RMW).
// Reduce via dp4a byte selectors; pcnt stored as uint4 (coalesced STS.128,
// conflict-free combine reads). Prefetch of row r+GRID_P into freed regs.
// ---------------------------------------------------------------------------
__global__ __launch_bounds__(NT, 2) void hist_kernel(const float* __restrict__ x,
                                                     const float* __restrict__ bias,
                                                     float* __restrict__ out) {
    extern __shared__ unsigned char smem[];
    unsigned char* s_hist = smem + SM_HIST;
    float* s_red = (float*)(smem + SM_RED);
    uint4* s_pcnt4 = (uint4*)(smem + SM_PCNT);
    float* s_cnt = (float*)(smem + SM_CNT);
    float* s_part = (float*)(smem + SM_PART);

    const int tid = threadIdx.x;
    const int w = tid >> 5;
    const int l = tid & 31;
    int row = blockIdx.x;

    // ---- Prologue: load first row into registers (8 float4/thread) ----
    float4 rv[8];
    {
        const float4* __restrict__ xr = (const float4*)(x + (size_t)row * F_DIM);
#pragma unroll
        for (int i = 0; i < 8; i++) rv[i] = __ldcs(xr + tid + i * NT);
    }

    for (;;) {
        const int next = row + GRID_P;
        const bool has_next = (next < N_ROWS);
        const float4* __restrict__ nxt =
            (const float4*)(x + (size_t)(has_next ? next : row) * F_DIM);

        // ---- Warp min/max partial ----
        float mn = f_inf(), mx = -f_inf();
#pragma unroll
        for (int i = 0; i < 8; i++) {
            mn = fminf(mn, fminf(fminf(rv[i].x, rv[i].y), fminf(rv[i].z, rv[i].w)));
            mx = fmaxf(mx, fmaxf(fmaxf(rv[i].x, rv[i].y), fmaxf(rv[i].z, rv[i].w)));
        }
#pragma unroll
        for (int o = 16; o > 0; o >>= 1) {
            mn = fminf(mn, __shfl_xor_sync(0xFFFFFFFFu, mn, o));
            mx = fmaxf(mx, __shfl_xor_sync(0xFFFFFFFFu, mx, o));
        }
        if (l == 0) { s_red[w] = mn; s_red[NW + w] = mx; }
        __syncthreads();                               // JOIN A

        // Fold 16 warp partials: lane reads one partial, shfl-reduce over 16
        {
            float a = s_red[l & 15];
            float b = s_red[NW + (l & 15)];
#pragma unroll
            for (int o = 8; o > 0; o >>= 1) {
                a = fminf(a, __shfl_xor_sync(0xFFFFFFFFu, a, o));
                b = fmaxf(b, __shfl_xor_sync(0xFFFFFFFFu, b, o));
            }
            mn = a; mx = b;
        }
        const float width = mx - mn;
        const float scale = 128.0f / (width == 0.0f ? 1.0f : width);  // matches jnp where()
        const float nb = -mn * scale;

        // ---- Zero own warp hist: 8 STS.128, lanes spread across banks ----
        {
            uint4* hz = (uint4*)(s_hist + (w << 12));
            uint4 z = make_uint4(0u, 0u, 0u, 0u);
#pragma unroll
            for (int k = 0; k < 8; k++) hz[k * 32 + l] = z;
        }
        __syncwarp();

        // ---- Bin 32 values (warp-local, bank-CF); interleave prefetch ----
        unsigned char* hb = s_hist + (w << 12) + (l << 2);
#pragma unroll
        for (int i = 0; i < 8; i++) {
            const float4 v = rv[i];
            if (has_next) rv[i] = __ldcs(nxt + tid + i * NT);   // prefetch
            const int b0 = (int)fminf(fmaf(v.x, scale, nb), 127.0f);
            const int b1 = (int)fminf(fmaf(v.y, scale, nb), 127.0f);
            const int b2 = (int)fminf(fmaf(v.z, scale, nb), 127.0f);
            const int b3 = (int)fminf(fmaf(v.w, scale, nb), 127.0f);
            // byte offset: (b>>2)*128 + (b&3) = ((b & 124) << 5) + (b & 3)
            const int o0 = ((b0 & 124) << 5) + (b0 & 3);
            const int o1 = ((b1 & 124) << 5) + (b1 & 3);
            const int o2 = ((b2 & 124) << 5) + (b2 & 3);
            const int o3 = ((b3 & 124) << 5) + (b3 & 3);
            const unsigned int e02 = (b2 == b0) ? 1u : 0u;
            const unsigned int e13 = (b3 == b1) ? 1u : 0u;
            // wave 1: loads of b0,b2 concurrent -> merged if equal
            unsigned int c0 = hb[o0];
            unsigned int c2 = hb[o2];
            hb[o0] = (unsigned char)(c0 + 1u + e02);
            if (!e02) hb[o2] = (unsigned char)(c2 + 1u);
            // wave 2: loads of b1,b3 after wave-1 stores (char aliasing)
            unsigned int c1 = hb[o1];
            unsigned int c3 = hb[o3];
            hb[o1] = (unsigned char)(c1 + 1u + e13);
            if (!e13) hb[o3] = (unsigned char)(c3 + 1u);
        }
        __syncwarp();

        // ---- Warp-local reduce: lane l owns bins 4l..4l+3 (word row l).
        // Rotated reads (bank (j+l)&31, CF); dp4a byte selectors split the
        // four bins packed per word. Max 32*32 = 1024 per bin: fits int.
        {
            const unsigned int* h32 = (const unsigned int*)(s_hist + (w << 12));
            unsigned int s0 = 0u, s1 = 0u, s2 = 0u, s3 = 0u;
#pragma unroll
            for (int j = 0; j < 32; j++) {
                const unsigned int v32 = h32[(l << 5) + ((j + l) & 31)];
                s0 = __dp4a(v32, 0x00000001u, s0);
                s1 = __dp4a(v32, 0x00000100u, s1);
                s2 = __dp4a(v32, 0x00010000u, s2);
                s3 = __dp4a(v32, 0x01000000u, s3);
            }
            // Packed store: bins 4l..4l+3 as one uint4 -> coalesced STS.128
            s_pcnt4[w * 33 + l] = make_uint4(s0, s1, s2, s3);
        }
        __syncthreads();                               // JOIN B

        // ---- Combine the 16 warps' partials.
        // Word index of (warp w2, bin b) = w2*132 + b -> banks CF across b.
        if (tid < N_BINS) {
            const unsigned int* p32 = (const unsigned int*)s_pcnt4;
            int s = 0;
#pragma unroll
            for (int w2 = 0; w2 < NW; w2++) s += (int)p32[w2 * 132 + tid];
            s_cnt[tid] = (float)s;
        }
        __syncthreads();                               // JOIN B2

        // ---- Epilogue: out[row][o] = cnt.Wt/F + mn*S0 + wd*S1 + b ----
        {
            const int o = tid & 63;
            const int q = tid >> 6;                    // 8 chunks of 16 bins
            const float* wt = g_wt + (q * 16) * N_OUT + o;
            float acc = 0.0f;
#pragma unroll
            for (int j = 0; j < 16; j++)
                acc = fmaf(s_cnt[q * 16 + j], __ldg(wt + j * N_OUT), acc);
            s_part[tid] = acc;
        }
        __syncthreads();                               // JOIN C
        if (tid < 64) {
            const float bo = bias[tid];
            float s = 0.0f;
#pragma unroll
            for (int k = 0; k < 8; k++) s += s_part[tid + 64 * k];
            float res = fmaf(s, 1.0f / 16384.0f,
                             fmaf(mn, g_s0[tid], fmaf(width, g_s1[tid], bo)));
            out[(size_t)row * N_OUT + tid] = res;
        }

        if (!has_next) break;
        row = next;
    }
}

// ---------------------------------------------------------------------------
extern "C" void kernel_launch(void* const* d_in, const int* in_sizes, int n_in,
                              void* d_out, int out_size) {
    const float* x = (const float*)d_in[0];
    const float* W = (const float*)d_in[1];
    const float* b = (const float*)d_in[2];
    float* out = (float*)d_out;

    cudaFuncSetAttribute(hist_kernel, cudaFuncAttributeMaxDynamicSharedMemorySize,
                         SM_TOTAL);

    prep_kernel<<<N_OUT, 128>>>(W);
    hist_kernel<<<GRID_P, NT, SM_TOTAL>>>(x, b, out);
}